// round 1
// baseline (speedup 1.0000x reference)
#include <cuda_runtime.h>
#include <cuda_bf16.h>
#include <cstdint>

// Problem constants (match reference)
#define N_B   16
#define T_DIM 4096
#define F_DIM 256
#define PAD_MAX 1228            // int(0.3 * 4096)
#define TP    (T_DIM + 2 * PAD_MAX)   // 6552

#define F_VEC (F_DIM / 4)       // 64 float4 per row
#define OUT_ELEMS (N_B * TP * F_DIM)  // 26,836,992
#define ROW_VECS_PER_N (TP * F_VEC)   // 419,328

__global__ __launch_bounds__(256)
void random_shift_kernel(const float* __restrict__ in_,
                         const int*   __restrict__ in_lens,
                         const int*   __restrict__ pad,
                         float* __restrict__ out)
{
    // one thread = one float4 of output
    unsigned v = blockIdx.x * 256u + threadIdx.x;   // < N_B * TP * F_VEC
    unsigned n   = v / ROW_VECS_PER_N;
    unsigned rem = v - n * ROW_VECS_PER_N;
    int t  = (int)(rem >> 6);        // rem / F_VEC  (F_VEC = 64)
    int f4 = (int)(rem & 63);

    int lens = __ldg(&in_lens[n]);
    int p0   = __ldg(&pad[n]);
    int p1   = __ldg(&pad[N_B + n]);
    int out_len = lens + p0 + p1;

    float4 val;
    if (t < out_len) {
        int src;
        if (t < p0) {
            src = p0 - t;                       // left reflect
        } else if (t < p0 + lens) {
            src = t - p0;                       // middle
        } else {
            src = 2 * lens + p0 - t - 2;        // right reflect
        }
        src = min(max(src, 0), T_DIM - 1);
        const float4* src_row = reinterpret_cast<const float4*>(
            in_ + ((size_t)n * T_DIM + (size_t)src) * F_DIM);
        val = __ldg(&src_row[f4]);
    } else {
        val = make_float4(0.f, 0.f, 0.f, 0.f);  // d_out poisoned -> must zero
    }

    reinterpret_cast<float4*>(out)[v] = val;
}

// Tail: out_lens packed after the main tensor (written as float; values are
// exact integers <= 6552 so fp32 representation is lossless).
__global__ void out_lens_kernel(const int* __restrict__ in_lens,
                                const int* __restrict__ pad,
                                float* __restrict__ out_tail,
                                int count)
{
    int i = threadIdx.x;
    if (i < count && i < N_B) {
        int ol = in_lens[i] + pad[i] + pad[N_B + i];
        out_tail[i] = (float)ol;
    }
}

extern "C" void kernel_launch(void* const* d_in, const int* in_sizes, int n_in,
                              void* d_out, int out_size)
{
    const float* in_    = (const float*)d_in[0];
    const int*   lens   = (const int*)d_in[1];
    const int*   pad    = (const int*)d_in[2];
    float*       out    = (float*)d_out;

    // 26,836,992 floats = 6,709,248 float4 = 26,208 blocks of 256 (exact)
    const int total_vec = OUT_ELEMS / 4;
    const int threads = 256;
    const int blocks = total_vec / threads;
    random_shift_kernel<<<blocks, threads>>>(in_, lens, pad, out);

    if (out_size > OUT_ELEMS) {
        int tail = out_size - OUT_ELEMS;
        out_lens_kernel<<<1, 32>>>(lens, pad, out + OUT_ELEMS, tail);
    }
}

// round 2
// speedup vs baseline: 1.0379x; 1.0379x over previous
#include <cuda_runtime.h>
#include <cuda_bf16.h>
#include <cstdint>

// Problem constants (match reference)
#define N_B   16
#define T_DIM 4096
#define F_DIM 256
#define PAD_MAX 1228                   // int(0.3 * 4096)
#define TP    (T_DIM + 2 * PAD_MAX)    // 6552

#define F_VEC (F_DIM / 4)              // 64 float4 per row
#define OUT_ELEMS (N_B * TP * F_DIM)   // 26,836,992
#define VECS_PER_N (TP * F_VEC)        // 419,328
#define BLOCKS_PER_N (VECS_PER_N / 256)  // 1638 (exact)

__global__ __launch_bounds__(256)
void random_shift_kernel(const float* __restrict__ in_,
                         const int*   __restrict__ in_lens,
                         const int*   __restrict__ pad,
                         float* __restrict__ out,
                         int tail_count)
{
    // 2D grid: y = batch index n, x = float4-vector index within batch row-block
    const int n = blockIdx.y;
    unsigned rem = blockIdx.x * 256u + threadIdx.x;   // < VECS_PER_N
    int t  = (int)(rem >> 6);        // rem / 64
    int f4 = (int)(rem & 63);

    int lens = __ldg(&in_lens[n]);
    int p0   = __ldg(&pad[n]);
    int p1   = __ldg(&pad[N_B + n]);
    int out_len = lens + p0 + p1;

    float4 val;
    if (t < out_len) {
        int src;
        if (t < p0) {
            src = p0 - t;                       // left reflect
        } else if (t < p0 + lens) {
            src = t - p0;                       // middle
        } else {
            src = 2 * lens + p0 - t - 2;        // right reflect
        }
        src = min(max(src, 0), T_DIM - 1);
        const float4* src_row = reinterpret_cast<const float4*>(
            in_ + ((size_t)n * T_DIM + (size_t)src) * F_DIM);
        val = __ldg(&src_row[f4]);
    } else {
        val = make_float4(0.f, 0.f, 0.f, 0.f);  // d_out poisoned -> must zero
    }

    reinterpret_cast<float4*>(out)[(size_t)n * VECS_PER_N + rem] = val;

    // Fold the out_lens tail write into the first block (no 2nd launch).
    // Values are exact integers <= 6552, lossless in fp32.
    if (blockIdx.x == 0 && blockIdx.y == 0 && threadIdx.x < 16) {
        int i = threadIdx.x;
        if (i < tail_count) {
            int ol = __ldg(&in_lens[i]) + __ldg(&pad[i]) + __ldg(&pad[N_B + i]);
            out[OUT_ELEMS + i] = (float)ol;
        }
    }
}

extern "C" void kernel_launch(void* const* d_in, const int* in_sizes, int n_in,
                              void* d_out, int out_size)
{
    const float* in_  = (const float*)d_in[0];
    const int*   lens = (const int*)d_in[1];
    const int*   pad  = (const int*)d_in[2];
    float*       out  = (float*)d_out;

    int tail = out_size - OUT_ELEMS;   // out_lens packed after main tensor (if present)
    if (tail < 0) tail = 0;

    dim3 grid(BLOCKS_PER_N, N_B, 1);   // 1638 x 16 = 26,208 blocks, exact
    random_shift_kernel<<<grid, 256>>>(in_, lens, pad, out, tail);
}

// round 3
// speedup vs baseline: 1.0816x; 1.0421x over previous
#include <cuda_runtime.h>
#include <cuda_bf16.h>
#include <cstdint>

// Problem constants (match reference)
#define N_B   16
#define T_DIM 4096
#define F_DIM 256
#define PAD_MAX 1228                   // int(0.3 * 4096)
#define TP    (T_DIM + 2 * PAD_MAX)    // 6552

#define F_VEC (F_DIM / 4)              // 64 float4 per row
#define OUT_ELEMS (N_B * TP * F_DIM)   // 26,836,992
#define VECS_PER_N (TP * F_VEC)        // 419,328
#define TOTAL_VEC (OUT_ELEMS / 4)      // 6,709,248
#define ILP 4
#define CHUNK (TOTAL_VEC / ILP)        // 1,677,312 = 4 * VECS_PER_N (exact)
#define NBLOCKS (CHUNK / 256)          // 6552 (exact)

__global__ __launch_bounds__(256)
void random_shift_kernel(const float* __restrict__ in_,
                         const int*   __restrict__ in_lens,
                         const int*   __restrict__ pad,
                         float* __restrict__ out,
                         int tail_count)
{
    const unsigned i = blockIdx.x * 256u + threadIdx.x;   // < CHUNK

    unsigned vv[ILP];
    const float4* srcp[ILP];
    bool valid[ILP];

    // Phase 1: compute all source addresses (independent chains)
    #pragma unroll
    for (int k = 0; k < ILP; k++) {
        unsigned v = i + (unsigned)k * CHUNK;
        unsigned n   = v / VECS_PER_N;          // warp-uniform
        unsigned rem = v - n * VECS_PER_N;
        int t  = (int)(rem >> 6);               // rem / 64
        int f4 = (int)(rem & 63);

        int lens = __ldg(&in_lens[n]);
        int p0   = __ldg(&pad[n]);
        int p1   = __ldg(&pad[N_B + n]);
        int out_len = lens + p0 + p1;

        int src;
        if (t < p0)              src = p0 - t;               // left reflect
        else if (t < p0 + lens)  src = t - p0;                // middle
        else                     src = 2 * lens + p0 - t - 2; // right reflect
        src = min(max(src, 0), T_DIM - 1);

        vv[k]    = v;
        valid[k] = (t < out_len);
        srcp[k]  = reinterpret_cast<const float4*>(
                       in_ + ((size_t)n * T_DIM + (size_t)src) * F_DIM) + f4;
    }

    // Phase 2: issue all loads (batched -> MLP=4)
    float4 val[ILP];
    #pragma unroll
    for (int k = 0; k < ILP; k++) {
        val[k] = valid[k] ? __ldg(srcp[k])
                          : make_float4(0.f, 0.f, 0.f, 0.f);
    }

    // Phase 3: stores (fully coalesced per instruction)
    #pragma unroll
    for (int k = 0; k < ILP; k++) {
        reinterpret_cast<float4*>(out)[vv[k]] = val[k];
    }

    // Fold out_lens tail write into the first block (values exact in fp32).
    if (blockIdx.x == 0 && threadIdx.x < 16) {
        int ix = threadIdx.x;
        if (ix < tail_count) {
            int ol = __ldg(&in_lens[ix]) + __ldg(&pad[ix]) + __ldg(&pad[N_B + ix]);
            out[OUT_ELEMS + ix] = (float)ol;
        }
    }
}

extern "C" void kernel_launch(void* const* d_in, const int* in_sizes, int n_in,
                              void* d_out, int out_size)
{
    const float* in_  = (const float*)d_in[0];
    const int*   lens = (const int*)d_in[1];
    const int*   pad  = (const int*)d_in[2];
    float*       out  = (float*)d_out;

    int tail = out_size - OUT_ELEMS;   // out_lens packed after main tensor (if present)
    if (tail < 0) tail = 0;

    random_shift_kernel<<<NBLOCKS, 256>>>(in_, lens, pad, out, tail);
}

// round 4
// speedup vs baseline: 1.1143x; 1.0302x over previous
#include <cuda_runtime.h>
#include <cuda_bf16.h>
#include <cstdint>

// Problem constants (match reference)
#define N_B   16
#define T_DIM 4096
#define F_DIM 256
#define PAD_MAX 1228                   // int(0.3 * 4096)
#define TP    (T_DIM + 2 * PAD_MAX)    // 6552

#define OUT_ELEMS (N_B * TP * F_DIM)   // 26,836,992

#define ROWS_PER_WARP  3
#define WARPS_PER_BLK  8
#define ROWS_PER_BLK   (ROWS_PER_WARP * WARPS_PER_BLK)  // 24
#define BLOCKS_PER_N   (TP / ROWS_PER_BLK)              // 273 (exact: 6552/24)

__global__ __launch_bounds__(256)
void random_shift_kernel(const float* __restrict__ in_,
                         const int*   __restrict__ in_lens,
                         const int*   __restrict__ pad,
                         float* __restrict__ out,
                         int tail_count)
{
    const int n    = blockIdx.y;
    const int w    = threadIdx.x >> 5;
    const int lane = threadIdx.x & 31;

    // warp-uniform metadata (L1 broadcast hits)
    const int lens = __ldg(&in_lens[n]);
    const int p0   = __ldg(&pad[n]);
    const int p1   = __ldg(&pad[N_B + n]);
    const int out_len = lens + p0 + p1;

    const float* in_n  = in_ + (size_t)n * T_DIM * F_DIM;
    float*       out_n = out + (size_t)n * TP * F_DIM;

    const int t0 = blockIdx.x * ROWS_PER_BLK + w * ROWS_PER_WARP;

    // Phase 1: per-row uniform source computation
    const float4* sp[ROWS_PER_WARP];
    bool vld[ROWS_PER_WARP];
    #pragma unroll
    for (int r = 0; r < ROWS_PER_WARP; r++) {
        int t = t0 + r;
        int src;
        if (t < p0)              src = p0 - t;                // left reflect
        else if (t < p0 + lens)  src = t - p0;                 // middle
        else                     src = 2 * lens + p0 - t - 2;  // right reflect
        src = min(max(src, 0), T_DIM - 1);
        vld[r] = (t < out_len);
        sp[r]  = reinterpret_cast<const float4*>(in_n + (size_t)src * F_DIM) + lane;
    }

    // Phase 2: 6 independent 16B loads per thread (MLP = 6)
    float4 val[ROWS_PER_WARP][2];
    #pragma unroll
    for (int r = 0; r < ROWS_PER_WARP; r++) {
        #pragma unroll
        for (int h = 0; h < 2; h++) {
            val[r][h] = vld[r] ? __ldg(sp[r] + h * 32)
                               : make_float4(0.f, 0.f, 0.f, 0.f);
        }
    }

    // Phase 3: streaming stores (evict-first: protect input's L2 residency)
    #pragma unroll
    for (int r = 0; r < ROWS_PER_WARP; r++) {
        int t = t0 + r;
        float4* op = reinterpret_cast<float4*>(out_n + (size_t)t * F_DIM) + lane;
        #pragma unroll
        for (int h = 0; h < 2; h++) {
            __stcs(op + h * 32, val[r][h]);
        }
    }

    // Fold out_lens tail write into the first block (values exact in fp32).
    if (blockIdx.x == 0 && blockIdx.y == 0 && threadIdx.x < 16) {
        int ix = threadIdx.x;
        if (ix < tail_count) {
            int ol = __ldg(&in_lens[ix]) + __ldg(&pad[ix]) + __ldg(&pad[N_B + ix]);
            out[OUT_ELEMS + ix] = (float)ol;
        }
    }
}

extern "C" void kernel_launch(void* const* d_in, const int* in_sizes, int n_in,
                              void* d_out, int out_size)
{
    const float* in_  = (const float*)d_in[0];
    const int*   lens = (const int*)d_in[1];
    const int*   pad  = (const int*)d_in[2];
    float*       out  = (float*)d_out;

    int tail = out_size - OUT_ELEMS;   // out_lens packed after main tensor (if present)
    if (tail < 0) tail = 0;

    dim3 grid(BLOCKS_PER_N, N_B, 1);   // 273 x 16 = 4368 blocks
    random_shift_kernel<<<grid, 256>>>(in_, lens, pad, out, tail);
}